// round 1
// baseline (speedup 1.0000x reference)
#include <cuda_runtime.h>

// Problem dims
#define LDIM 128
#define BDIM 2048
#define DDIM 300
#define HDIM 60
#define HPAD 64
#define MDIM (LDIM * BDIM)  // 262144

// Scratch (static device globals — no allocation)
__device__ float  g_q[(size_t)MDIM * HPAD];   // projected, padded to 64 cols (pad cols are 0)
__device__ float2 g_w[MDIM];                  // (w0, w2) softmax weights; w1 = 1 - w0 - w2

// ---------------------------------------------------------------------------
// Kernel 1: q = sentence @ proj   ([M,300] x [300,60] -> [M,64], cols 60..63 = 0)
// Block tile 128x64, BK=20, thread tile 8x8, 128 threads.
// ---------------------------------------------------------------------------
#define GBM 128
#define GBN 64
#define GBK 20

__global__ __launch_bounds__(128, 4) void k_gemm(const float* __restrict__ A,
                                                 const float* __restrict__ P) {
    __shared__ float As[GBK][GBM];   // transposed: As[k][m]
    __shared__ float Bs[GBK][GBN];

    const int tid  = threadIdx.x;
    const int trow = tid >> 3;       // 0..15
    const int tcol = tid & 7;        // 0..7
    const int bm   = blockIdx.x * GBM;

    // zero the N-pad columns once (never rewritten inside the loop)
    if (tid < GBK) {
        Bs[tid][60] = 0.f; Bs[tid][61] = 0.f; Bs[tid][62] = 0.f; Bs[tid][63] = 0.f;
    }

    float acc[8][8];
#pragma unroll
    for (int i = 0; i < 8; i++)
#pragma unroll
        for (int j = 0; j < 8; j++) acc[i][j] = 0.f;

    const float* arow = A + (size_t)(bm + tid) * DDIM;

    for (int k0 = 0; k0 < DDIM; k0 += GBK) {
        __syncthreads();
        // A tile: thread tid owns global row bm+tid, loads its 20-float k-chunk
        // (5x float4). Stores to transposed smem are bank-conflict-free.
#pragma unroll
        for (int i = 0; i < 5; i++) {
            float4 v = *reinterpret_cast<const float4*>(arow + k0 + 4 * i);
            As[4 * i + 0][tid] = v.x;
            As[4 * i + 1][tid] = v.y;
            As[4 * i + 2][tid] = v.z;
            As[4 * i + 3][tid] = v.w;
        }
        // B tile: 20 rows x 60 cols = 300 float4
#pragma unroll
        for (int i = 0; i < 3; i++) {
            int f = tid + 128 * i;
            if (f < 300) {
                int kk = f / 15, q = f - kk * 15;
                float4 v = *reinterpret_cast<const float4*>(P + (size_t)(k0 + kk) * HDIM + 4 * q);
                *reinterpret_cast<float4*>(&Bs[kk][4 * q]) = v;
            }
        }
        __syncthreads();

#pragma unroll
        for (int k = 0; k < GBK; k++) {
            float a[8], b[8];
            *reinterpret_cast<float4*>(&a[0]) = *reinterpret_cast<const float4*>(&As[k][trow * 8]);
            *reinterpret_cast<float4*>(&a[4]) = *reinterpret_cast<const float4*>(&As[k][trow * 8 + 4]);
            *reinterpret_cast<float4*>(&b[0]) = *reinterpret_cast<const float4*>(&Bs[k][tcol * 8]);
            *reinterpret_cast<float4*>(&b[4]) = *reinterpret_cast<const float4*>(&Bs[k][tcol * 8 + 4]);
#pragma unroll
            for (int i = 0; i < 8; i++)
#pragma unroll
                for (int j = 0; j < 8; j++) acc[i][j] = fmaf(a[i], b[j], acc[i][j]);
        }
    }

#pragma unroll
    for (int i = 0; i < 8; i++) {
        size_t m = (size_t)bm + trow * 8 + i;
        float4 v0 = make_float4(acc[i][0], acc[i][1], acc[i][2], acc[i][3]);
        float4 v1 = make_float4(acc[i][4], acc[i][5], acc[i][6], acc[i][7]);
        *reinterpret_cast<float4*>(g_q + m * HPAD + tcol * 8)     = v0;
        *reinterpret_cast<float4*>(g_q + m * HPAD + tcol * 8 + 4) = v1;
    }
}

// ---------------------------------------------------------------------------
// Kernel 2: per-b column — row norms, neighbor dots, masked 3-way softmax.
// One block (128 threads = 4 warps) per b. Warp w scans rows 32w..32w+31,
// carrying the previous row in registers to form the cross-dot.
// ---------------------------------------------------------------------------
__global__ __launch_bounds__(128) void k_simw(const int* __restrict__ size) {
    const int b    = blockIdx.x;
    const int tid  = threadIdx.x;
    const int w    = tid >> 5;
    const int lane = tid & 31;

    __shared__ float nrm[LDIM];
    __shared__ float crs[LDIM];   // crs[l] = <q_l, q_{l+1}>, valid l=0..126

    const int r0 = w * 32;
    float p0 = 0.f, p1 = 0.f;
    if (w > 0) {
        const float* row = g_q + ((size_t)(r0 - 1) * BDIM + b) * HPAD;
        p0 = row[lane];
        p1 = row[lane + 32];
    }
    for (int r = r0; r < r0 + 32; ++r) {
        const float* row = g_q + ((size_t)r * BDIM + b) * HPAD;
        float v0 = row[lane], v1 = row[lane + 32];
        float nn = v0 * v0 + v1 * v1;
        float cc = v0 * p0 + v1 * p1;
#pragma unroll
        for (int off = 16; off; off >>= 1) {
            nn += __shfl_xor_sync(0xffffffffu, nn, off);
            cc += __shfl_xor_sync(0xffffffffu, cc, off);
        }
        if (lane == 0) {
            nrm[r] = fmaxf(nn, 1e-5f);
            if (r > 0) crs[r - 1] = cc;
        }
        p0 = v0; p1 = v1;
    }
    __syncthreads();

    const int l  = tid;
    const int sz = size[b];
    float a0 = -1e30f, a2 = -1e30f;
    if (l >= 1 && l < sz)                  // prev-channel valid
        a0 = crs[l - 1] / (nrm[l - 1] * nrm[l]);
    int lim2 = sz - 1; if (lim2 < 0) lim2 = 0;
    if (l < lim2)                          // next-channel valid (lim2 <= 126)
        a2 = crs[l] / (nrm[l] * nrm[l + 1]);

    float mx = fmaxf(1.0f, fmaxf(a0, a2));
    float e0 = expf(a0 - mx);
    float e1 = expf(1.0f - mx);
    float e2 = expf(a2 - mx);
    float inv = 1.0f / (e0 + e1 + e2);
    g_w[l * BDIM + b] = make_float2(e0 * inv, e2 * inv);
}

// ---------------------------------------------------------------------------
// Kernel 3: out[l,b,:] = w1*s[l,b,:] + w0*s[l-1,b,:] + w2*s[l+1,b,:]
// One float4 per thread; 75 float4 per (l,b) row.
// ---------------------------------------------------------------------------
__global__ __launch_bounds__(256) void k_combine(const float* __restrict__ S,
                                                 float* __restrict__ out) {
    const int idx = blockIdx.x * 256 + threadIdx.x;   // < 19,660,800
    const int lb  = idx / 75;
    const int j   = idx - lb * 75;
    const int l   = lb >> 11;

    float2 ww = g_w[lb];
    const float w0 = ww.x, w2 = ww.y;
    const float w1 = 1.0f - w0 - w2;

    const float4* s4 = reinterpret_cast<const float4*>(S);
    const size_t base = (size_t)lb * 75 + j;

    float4 c = s4[base];
    float4 r;
    r.x = w1 * c.x; r.y = w1 * c.y; r.z = w1 * c.z; r.w = w1 * c.w;
    if (l > 0) {
        float4 p = s4[base - (size_t)BDIM * 75];
        r.x = fmaf(w0, p.x, r.x); r.y = fmaf(w0, p.y, r.y);
        r.z = fmaf(w0, p.z, r.z); r.w = fmaf(w0, p.w, r.w);
    }
    if (l < LDIM - 1) {
        float4 n = s4[base + (size_t)BDIM * 75];
        r.x = fmaf(w2, n.x, r.x); r.y = fmaf(w2, n.y, r.y);
        r.z = fmaf(w2, n.z, r.z); r.w = fmaf(w2, n.w, r.w);
    }
    reinterpret_cast<float4*>(out)[base] = r;
}

// ---------------------------------------------------------------------------
extern "C" void kernel_launch(void* const* d_in, const int* in_sizes, int n_in,
                              void* d_out, int out_size) {
    const float* sentence = nullptr;
    const int*   size_arr = nullptr;
    const float* proj     = nullptr;
    for (int i = 0; i < n_in; ++i) {
        if (in_sizes[i] == LDIM * BDIM * DDIM)      sentence = (const float*)d_in[i];
        else if (in_sizes[i] == DDIM * HDIM)        proj     = (const float*)d_in[i];
        else if (in_sizes[i] == BDIM)               size_arr = (const int*)d_in[i];
    }
    float* out = (float*)d_out;

    k_gemm<<<MDIM / GBM, 128>>>(sentence, proj);               // 2048 blocks
    k_simw<<<BDIM, 128>>>(size_arr);                           // 2048 blocks
    k_combine<<<(LDIM * BDIM * (DDIM / 4)) / 256, 256>>>(sentence, out);  // 76800 blocks
}

// round 3
// speedup vs baseline: 1.1774x; 1.1774x over previous
#include <cuda_runtime.h>
#include <cstdint>

// Problem dims
#define LDIM 128
#define BDIM 2048
#define DDIM 300
#define HDIM 60
#define HPAD 64
#define MDIM (LDIM * BDIM)  // 262144

// Scratch (static device globals — no allocation)
__device__ float  g_q[(size_t)MDIM * HPAD];   // projected, padded to 64 cols
__device__ float2 g_w[MDIM];                  // (w0, w2); w1 = 1 - w0 - w2

// ---------------------------------------------------------------------------
// Kernel 1: q = sentence @ proj via mma.sync m16n8k8 tf32 (fallback HMMA path;
// tcgen05 is unavailable: harness PTX target is sm_103 without the 'a' suffix).
// Block 256 threads = 8 warps; tile M=128 (16 rows/warp), N=64, BK=32.
// K padded 300 -> 320 with zeros in smem.
// ---------------------------------------------------------------------------
#define KC    32
#define NCH   10          // ceil(300/32)
#define SAS   136         // sAT row stride (floats); 136 % 32 == 8 -> conflict-free frags
#define SBS   72          // sB row stride (floats); 72 % 32 == 8

__device__ __forceinline__ uint32_t f2tf32(float x) {
    uint32_t u;
    asm("cvt.rna.tf32.f32 %0, %1;" : "=r"(u) : "f"(x));
    return u;
}

__device__ __forceinline__ void mma_tf32(float* c, uint32_t a0, uint32_t a1,
                                         uint32_t a2, uint32_t a3,
                                         uint32_t b0, uint32_t b1) {
    asm volatile(
        "mma.sync.aligned.m16n8k8.row.col.f32.tf32.tf32.f32 "
        "{%0,%1,%2,%3}, {%4,%5,%6,%7}, {%8,%9}, {%0,%1,%2,%3};"
        : "+f"(c[0]), "+f"(c[1]), "+f"(c[2]), "+f"(c[3])
        : "r"(a0), "r"(a1), "r"(a2), "r"(a3), "r"(b0), "r"(b1));
}

__global__ __launch_bounds__(256, 3) void k_gemm_mma(const float* __restrict__ A,
                                                     const float* __restrict__ P) {
    __shared__ uint32_t sAT[KC * SAS];   // [k][m] transposed, tf32 bits, 17.4 KB
    __shared__ uint32_t sB [KC * SBS];   // [k][h] tf32 bits, 9.2 KB

    const int tid  = threadIdx.x;
    const int w    = tid >> 5;
    const int lane = tid & 31;
    const int g    = lane >> 2;     // groupID 0..7
    const int tig  = lane & 3;      // thread-in-group 0..3
    const int bm   = blockIdx.x * 128;

    // A staging ownership: thread t -> (row = t>>1, khalf = t&1), 16 floats each
    const int arow  = tid >> 1;
    const int ahalf = tid & 1;
    const float* agp = A + (size_t)(bm + arow) * DDIM + ahalf * 16;

    // B staging ownership: thread t -> (kk = t>>3, h0 = (t&7)*8), 8 floats each
    const int bkk = tid >> 3;
    const int bh0 = (tid & 7) * 8;

    float acc[8][4];
#pragma unroll
    for (int n = 0; n < 8; ++n)
#pragma unroll
        for (int i = 0; i < 4; ++i) acc[n][i] = 0.f;

    const int mrow0 = 16 * w + g;

    for (int c = 0; c < NCH; ++c) {
        const int k0 = c * KC;
        __syncthreads();

        // ---- stage A [128 x 32] -> sAT[k][m], tf32, zero-padded past K=300 ----
#pragma unroll
        for (int i = 0; i < 4; ++i) {
            const int k = k0 + ahalf * 16 + i * 4;
            float4 v = make_float4(0.f, 0.f, 0.f, 0.f);
            if (k + 4 <= DDIM)                       // 300 % 4 == 0: never partial
                v = *reinterpret_cast<const float4*>(agp + k0 + i * 4);
            const int kl = ahalf * 16 + i * 4;
            sAT[(kl + 0) * SAS + arow] = f2tf32(v.x);
            sAT[(kl + 1) * SAS + arow] = f2tf32(v.y);
            sAT[(kl + 2) * SAS + arow] = f2tf32(v.z);
            sAT[(kl + 3) * SAS + arow] = f2tf32(v.w);
        }
        // ---- stage B [32 x 64]: sB[k][h] = proj[k0+k][h], pad h>=60, k>=300 ----
        {
            const int kg = k0 + bkk;
            const float* prow = P + (size_t)kg * HDIM + bh0;
#pragma unroll
            for (int j = 0; j < 8; ++j) {
                float v = 0.f;
                if (kg < DDIM && bh0 + j < HDIM) v = prow[j];
                sB[bkk * SBS + bh0 + j] = f2tf32(v);
            }
        }
        __syncthreads();

        // ---- 4 k-steps of m16n8k8 per chunk ----
#pragma unroll
        for (int ks = 0; ks < 4; ++ks) {
            const int kk = ks * 8;
            const uint32_t a0 = sAT[(kk + tig) * SAS + mrow0];
            const uint32_t a1 = sAT[(kk + tig) * SAS + mrow0 + 8];
            const uint32_t a2 = sAT[(kk + tig + 4) * SAS + mrow0];
            const uint32_t a3 = sAT[(kk + tig + 4) * SAS + mrow0 + 8];
#pragma unroll
            for (int n = 0; n < 8; ++n) {
                const uint32_t b0 = sB[(kk + tig) * SBS + 8 * n + g];
                const uint32_t b1 = sB[(kk + tig + 4) * SBS + 8 * n + g];
                mma_tf32(acc[n], a0, a1, a2, a3, b0, b1);
            }
        }
    }

    // ---- epilogue: D fragment (c0,c1)=(row g, cols 2tig,2tig+1), (c2,c3)=row g+8
    float* dst0 = g_q + ((size_t)bm + mrow0) * HPAD;
    float* dst1 = g_q + ((size_t)bm + mrow0 + 8) * HPAD;
#pragma unroll
    for (int n = 0; n < 8; ++n) {
        const int col = 8 * n + 2 * tig;
        *reinterpret_cast<float2*>(dst0 + col) = make_float2(acc[n][0], acc[n][1]);
        *reinterpret_cast<float2*>(dst1 + col) = make_float2(acc[n][2], acc[n][3]);
    }
}

// ---------------------------------------------------------------------------
// Kernel 2: per-b column — row norms, neighbor dots, masked 3-way softmax.
// ---------------------------------------------------------------------------
__global__ __launch_bounds__(128) void k_simw(const int* __restrict__ size) {
    const int b    = blockIdx.x;
    const int tid  = threadIdx.x;
    const int w    = tid >> 5;
    const int lane = tid & 31;

    __shared__ float nrm[LDIM];
    __shared__ float crs[LDIM];

    const int r0 = w * 32;
    float p0 = 0.f, p1 = 0.f;
    if (w > 0) {
        const float* row = g_q + ((size_t)(r0 - 1) * BDIM + b) * HPAD;
        p0 = row[lane];
        p1 = row[lane + 32];
    }
    for (int r = r0; r < r0 + 32; ++r) {
        const float* row = g_q + ((size_t)r * BDIM + b) * HPAD;
        float v0 = row[lane], v1 = row[lane + 32];
        float nn = v0 * v0 + v1 * v1;
        float cc = v0 * p0 + v1 * p1;
#pragma unroll
        for (int off = 16; off; off >>= 1) {
            nn += __shfl_xor_sync(0xffffffffu, nn, off);
            cc += __shfl_xor_sync(0xffffffffu, cc, off);
        }
        if (lane == 0) {
            nrm[r] = fmaxf(nn, 1e-5f);
            if (r > 0) crs[r - 1] = cc;
        }
        p0 = v0; p1 = v1;
    }
    __syncthreads();

    const int l  = tid;
    const int sz = size[b];
    float a0 = -1e30f, a2 = -1e30f;
    if (l >= 1 && l < sz)
        a0 = crs[l - 1] / (nrm[l - 1] * nrm[l]);
    int lim2 = sz - 1; if (lim2 < 0) lim2 = 0;
    if (l < lim2)
        a2 = crs[l] / (nrm[l] * nrm[l + 1]);

    float mx = fmaxf(1.0f, fmaxf(a0, a2));
    float e0 = expf(a0 - mx);
    float e1 = expf(1.0f - mx);
    float e2 = expf(a2 - mx);
    float inv = 1.0f / (e0 + e1 + e2);
    g_w[l * BDIM + b] = make_float2(e0 * inv, e2 * inv);
}

// ---------------------------------------------------------------------------
// Kernel 3: out[l,b,:] = w1*s[l,b,:] + w0*s[l-1,b,:] + w2*s[l+1,b,:]
// ---------------------------------------------------------------------------
__global__ __launch_bounds__(256) void k_combine(const float* __restrict__ S,
                                                 float* __restrict__ out) {
    const int idx = blockIdx.x * 256 + threadIdx.x;
    const int lb  = idx / 75;
    const int j   = idx - lb * 75;
    const int l   = lb >> 11;

    float2 ww = g_w[lb];
    const float w0 = ww.x, w2 = ww.y;
    const float w1 = 1.0f - w0 - w2;

    const float4* s4 = reinterpret_cast<const float4*>(S);
    const size_t base = (size_t)lb * 75 + j;

    float4 c = s4[base];
    float4 r;
    r.x = w1 * c.x; r.y = w1 * c.y; r.z = w1 * c.z; r.w = w1 * c.w;
    if (l > 0) {
        float4 p = s4[base - (size_t)BDIM * 75];
        r.x = fmaf(w0, p.x, r.x); r.y = fmaf(w0, p.y, r.y);
        r.z = fmaf(w0, p.z, r.z); r.w = fmaf(w0, p.w, r.w);
    }
    if (l < LDIM - 1) {
        float4 n = s4[base + (size_t)BDIM * 75];
        r.x = fmaf(w2, n.x, r.x); r.y = fmaf(w2, n.y, r.y);
        r.z = fmaf(w2, n.z, r.z); r.w = fmaf(w2, n.w, r.w);
    }
    reinterpret_cast<float4*>(out)[base] = r;
}

// ---------------------------------------------------------------------------
extern "C" void kernel_launch(void* const* d_in, const int* in_sizes, int n_in,
                              void* d_out, int out_size) {
    const float* sentence = nullptr;
    const int*   size_arr = nullptr;
    const float* proj     = nullptr;
    for (int i = 0; i < n_in; ++i) {
        if (in_sizes[i] == LDIM * BDIM * DDIM)      sentence = (const float*)d_in[i];
        else if (in_sizes[i] == DDIM * HDIM)        proj     = (const float*)d_in[i];
        else if (in_sizes[i] == BDIM)               size_arr = (const int*)d_in[i];
    }
    float* out = (float*)d_out;

    k_gemm_mma<<<MDIM / 128, 256>>>(sentence, proj);
    k_simw<<<BDIM, 128>>>(size_arr);
    k_combine<<<(LDIM * BDIM * (DDIM / 4)) / 256, 256>>>(sentence, out);
}

// round 4
// speedup vs baseline: 1.4822x; 1.2589x over previous
#include <cuda_runtime.h>
#include <cstdint>

// Problem dims
#define LDIM 128
#define BDIM 2048
#define DDIM 300
#define HDIM 60
#define HPAD 64
#define MDIM (LDIM * BDIM)  // 262144

// GEMM tiling
#define KC   32            // K per chunk
#define NCH  10            // ceil(300/32), K padded to 320
#define MT   256           // M rows per block
#define SAS  36            // sA row stride (floats): bank = 4g+tig -> conflict-free

// Scratch (static device globals — no allocation)
__device__ float  g_q[(size_t)MDIM * HPAD];     // projected, padded to 64 cols
__device__ float2 g_w[MDIM];                    // (w0, w2); w1 = 1 - w0 - w2
__device__ float2 g_bpack[NCH * 1024];          // pre-packed B fragments per chunk

__device__ __forceinline__ uint32_t smem_u32(const void* p) {
    uint32_t a;
    asm("{ .reg .u64 t; cvta.to.shared.u64 t, %1; cvt.u32.u64 %0, t; }" : "=r"(a) : "l"(p));
    return a;
}
__device__ __forceinline__ uint32_t f2tf32(float x) {
    uint32_t u;
    asm("cvt.rna.tf32.f32 %0, %1;" : "=r"(u) : "f"(x));
    return u;
}
__device__ __forceinline__ void mma_tf32(float* c, uint32_t a0, uint32_t a1,
                                         uint32_t a2, uint32_t a3,
                                         uint32_t b0, uint32_t b1) {
    asm volatile(
        "mma.sync.aligned.m16n8k8.row.col.f32.tf32.tf32.f32 "
        "{%0,%1,%2,%3}, {%4,%5,%6,%7}, {%8,%9}, {%0,%1,%2,%3};"
        : "+f"(c[0]), "+f"(c[1]), "+f"(c[2]), "+f"(c[3])
        : "r"(a0), "r"(a1), "r"(a2), "r"(a3), "r"(b0), "r"(b1));
}
__device__ __forceinline__ void cp16(uint32_t dst, const void* src, int sz) {
    asm volatile("cp.async.cg.shared.global [%0], [%1], 16, %2;"
                 :: "r"(dst), "l"(src), "r"(sz));
}
#define CP_COMMIT() asm volatile("cp.async.commit_group;" ::: "memory")
#define CP_WAIT0()  asm volatile("cp.async.wait_group 0;" ::: "memory")

// ---------------------------------------------------------------------------
// Kernel 0 (one-shot, tiny): pack B fragments for all chunks.
// Entry e in chunk c: ks=e>>8, n=(e>>5)&7, lane=e&31 (tig=lane&3, g=lane>>2)
//   pair = ( P[c*32+8ks+tig][8n+g], P[c*32+8ks+tig+4][8n+g] ), zero-padded.
// ---------------------------------------------------------------------------
__global__ void k_packB(const float* __restrict__ P) {
    const int e = blockIdx.x * 256 + threadIdx.x;   // < 10240
    if (e >= NCH * 1024) return;
    const int c  = e >> 10;
    const int r  = e & 1023;
    const int ks = r >> 8;
    const int n  = (r >> 5) & 7;
    const int ln = r & 31;
    const int tg = ln & 3, g = ln >> 2;
    const int k  = c * KC + 8 * ks + tg;
    const int h  = 8 * n + g;
    float b0 = (k < DDIM && h < HDIM)     ? P[(size_t)k * HDIM + h]       : 0.f;
    float b1 = (k + 4 < DDIM && h < HDIM) ? P[(size_t)(k + 4) * HDIM + h] : 0.f;
    float2 v;
    v.x = __uint_as_float(f2tf32(b0));
    v.y = __uint_as_float(f2tf32(b1));
    g_bpack[e] = v;
}

// ---------------------------------------------------------------------------
// Kernel 1: q = sentence @ proj via m16n8k8 tf32, double-buffered cp.async A.
// 256 threads / 8 warps; M=256 per block (2 m16 tiles per warp), N=64.
// Dynamic smem: sA[2][256][36] + sBp[2][1024] float2 = 90112 B.
// ---------------------------------------------------------------------------
__global__ __launch_bounds__(256, 2) void k_gemm_mma(const float* __restrict__ A,
                                                     const float* __restrict__ P) {
    extern __shared__ float sm[];
    float*  sA  = sm;                                  // [2][MT][SAS]
    float2* sBp = reinterpret_cast<float2*>(sm + 2 * MT * SAS);  // [2][1024]
    const uint32_t* sAu = reinterpret_cast<const uint32_t*>(sm);

    const int tid  = threadIdx.x;
    const int w    = tid >> 5;
    const int lane = tid & 31;
    const int g    = lane >> 2;
    const int tig  = lane & 3;
    const int bm   = blockIdx.x * MT;

    const float*   arow   = A + (size_t)(bm + tid) * DDIM;  // staging: thread owns row tid
    const uint32_t sA_u   = smem_u32(sA);

    float acc0[8][4], acc1[8][4];
#pragma unroll
    for (int n = 0; n < 8; ++n)
#pragma unroll
        for (int i = 0; i < 4; ++i) { acc0[n][i] = 0.f; acc1[n][i] = 0.f; }

    // ---- staging lambdas (inlined manually) ----
    // stage A chunk c into buffer buf: 8 x cp.async(16B), zero-fill past K=300
    auto stageA = [&](int c, int buf) {
#pragma unroll
        for (int i = 0; i < 8; ++i) {
            const int k  = c * KC + 4 * i;
            const int sz = (k + 4 <= DDIM) ? 16 : 0;
            const float* src = sz ? (arow + k) : A;   // any valid addr when sz==0
            const uint32_t dst = sA_u + (((buf * MT + tid) * SAS + 4 * i) << 2);
            cp16(dst, src, sz);
        }
    };
    auto stageB = [&](int c, int buf) {
#pragma unroll
        for (int e = 0; e < 4; ++e) {
            const int idx = tid + 256 * e;
            sBp[buf * 1024 + idx] = g_bpack[c * 1024 + idx];
        }
    };

    // prologue
    stageA(0, 0);
    CP_COMMIT();
    stageB(0, 0);

    const int rbase = 32 * w + g;   // tile0 row for this thread (tile1 = +16)

    for (int c = 0; c < NCH; ++c) {
        const int buf = c & 1;
        CP_WAIT0();          // A(c) arrived (stage(c+1) not yet issued)
        __syncthreads();     // all warps done with mma(c-1); B(c) STS visible

        if (c + 1 < NCH) {   // overlap: fill other buffer while mma(c) runs
            stageA(c + 1, buf ^ 1);
            CP_COMMIT();
            stageB(c + 1, buf ^ 1);
        }

#pragma unroll
        for (int ks = 0; ks < 4; ++ks) {
            const int kk = 8 * ks;
            const int r0 = (buf * MT + rbase) * SAS + kk + tig;
            const uint32_t a00 = sAu[r0];
            const uint32_t a01 = sAu[r0 + 8 * SAS];
            const uint32_t a02 = sAu[r0 + 4];
            const uint32_t a03 = sAu[r0 + 8 * SAS + 4];
            const uint32_t a10 = sAu[r0 + 16 * SAS];
            const uint32_t a11 = sAu[r0 + 24 * SAS];
            const uint32_t a12 = sAu[r0 + 16 * SAS + 4];
            const uint32_t a13 = sAu[r0 + 24 * SAS + 4];
#pragma unroll
            for (int n = 0; n < 8; ++n) {
                const float2 b = sBp[buf * 1024 + (ks * 8 + n) * 32 + lane];
                const uint32_t b0 = __float_as_uint(b.x);
                const uint32_t b1 = __float_as_uint(b.y);
                mma_tf32(acc0[n], a00, a01, a02, a03, b0, b1);
                mma_tf32(acc1[n], a10, a11, a12, a13, b0, b1);
            }
        }
    }

    // ---- epilogue: c0,c1 = (row g, cols 2tig,2tig+1); c2,c3 = row g+8 ----
    float* d00 = g_q + ((size_t)bm + rbase) * HPAD;
    float* d01 = g_q + ((size_t)bm + rbase + 8) * HPAD;
    float* d10 = g_q + ((size_t)bm + rbase + 16) * HPAD;
    float* d11 = g_q + ((size_t)bm + rbase + 24) * HPAD;
#pragma unroll
    for (int n = 0; n < 8; ++n) {
        const int col = 8 * n + 2 * tig;
        *reinterpret_cast<float2*>(d00 + col) = make_float2(acc0[n][0], acc0[n][1]);
        *reinterpret_cast<float2*>(d01 + col) = make_float2(acc0[n][2], acc0[n][3]);
        *reinterpret_cast<float2*>(d10 + col) = make_float2(acc1[n][0], acc1[n][1]);
        *reinterpret_cast<float2*>(d11 + col) = make_float2(acc1[n][2], acc1[n][3]);
    }
}

// ---------------------------------------------------------------------------
// Kernel 2: per-b column — row norms, neighbor dots, masked 3-way softmax.
// ---------------------------------------------------------------------------
__global__ __launch_bounds__(128) void k_simw(const int* __restrict__ size) {
    const int b    = blockIdx.x;
    const int tid  = threadIdx.x;
    const int w    = tid >> 5;
    const int lane = tid & 31;

    __shared__ float nrm[LDIM];
    __shared__ float crs[LDIM];

    const int r0 = w * 32;
    float p0 = 0.f, p1 = 0.f;
    if (w > 0) {
        const float* row = g_q + ((size_t)(r0 - 1) * BDIM + b) * HPAD;
        p0 = row[lane];
        p1 = row[lane + 32];
    }
    for (int r = r0; r < r0 + 32; ++r) {
        const float* row = g_q + ((size_t)r * BDIM + b) * HPAD;
        float v0 = row[lane], v1 = row[lane + 32];
        float nn = v0 * v0 + v1 * v1;
        float cc = v0 * p0 + v1 * p1;
#pragma unroll
        for (int off = 16; off; off >>= 1) {
            nn += __shfl_xor_sync(0xffffffffu, nn, off);
            cc += __shfl_xor_sync(0xffffffffu, cc, off);
        }
        if (lane == 0) {
            nrm[r] = fmaxf(nn, 1e-5f);
            if (r > 0) crs[r - 1] = cc;
        }
        p0 = v0; p1 = v1;
    }
    __syncthreads();

    const int l  = tid;
    const int sz = size[b];
    float a0 = -1e30f, a2 = -1e30f;
    if (l >= 1 && l < sz)
        a0 = crs[l - 1] / (nrm[l - 1] * nrm[l]);
    int lim2 = sz - 1; if (lim2 < 0) lim2 = 0;
    if (l < lim2)
        a2 = crs[l] / (nrm[l] * nrm[l + 1]);

    float mx = fmaxf(1.0f, fmaxf(a0, a2));
    float e0 = expf(a0 - mx);
    float e1 = expf(1.0f - mx);
    float e2 = expf(a2 - mx);
    float inv = 1.0f / (e0 + e1 + e2);
    g_w[l * BDIM + b] = make_float2(e0 * inv, e2 * inv);
}

// ---------------------------------------------------------------------------
// Kernel 3: out[l,b,:] = w1*s[l,b,:] + w0*s[l-1,b,:] + w2*s[l+1,b,:]
// ---------------------------------------------------------------------------
__global__ __launch_bounds__(256) void k_combine(const float* __restrict__ S,
                                                 float* __restrict__ out) {
    const int idx = blockIdx.x * 256 + threadIdx.x;
    const int lb  = idx / 75;
    const int j   = idx - lb * 75;
    const int l   = lb >> 11;

    float2 ww = g_w[lb];
    const float w0 = ww.x, w2 = ww.y;
    const float w1 = 1.0f - w0 - w2;

    const float4* s4 = reinterpret_cast<const float4*>(S);
    const size_t base = (size_t)lb * 75 + j;

    float4 c = s4[base];
    float4 r;
    r.x = w1 * c.x; r.y = w1 * c.y; r.z = w1 * c.z; r.w = w1 * c.w;
    if (l > 0) {
        float4 p = s4[base - (size_t)BDIM * 75];
        r.x = fmaf(w0, p.x, r.x); r.y = fmaf(w0, p.y, r.y);
        r.z = fmaf(w0, p.z, r.z); r.w = fmaf(w0, p.w, r.w);
    }
    if (l < LDIM - 1) {
        float4 n = s4[base + (size_t)BDIM * 75];
        r.x = fmaf(w2, n.x, r.x); r.y = fmaf(w2, n.y, r.y);
        r.z = fmaf(w2, n.z, r.z); r.w = fmaf(w2, n.w, r.w);
    }
    reinterpret_cast<float4*>(out)[base] = r;
}

// ---------------------------------------------------------------------------
extern "C" void kernel_launch(void* const* d_in, const int* in_sizes, int n_in,
                              void* d_out, int out_size) {
    const float* sentence = nullptr;
    const int*   size_arr = nullptr;
    const float* proj     = nullptr;
    for (int i = 0; i < n_in; ++i) {
        if (in_sizes[i] == LDIM * BDIM * DDIM)      sentence = (const float*)d_in[i];
        else if (in_sizes[i] == DDIM * HDIM)        proj     = (const float*)d_in[i];
        else if (in_sizes[i] == BDIM)               size_arr = (const int*)d_in[i];
    }
    float* out = (float*)d_out;

    const int smem_bytes = (2 * MT * SAS) * 4 + 2 * 1024 * 8;   // 90112
    cudaFuncSetAttribute(k_gemm_mma, cudaFuncAttributeMaxDynamicSharedMemorySize,
                         smem_bytes);

    k_packB<<<(NCH * 1024 + 255) / 256, 256>>>(proj);
    k_gemm_mma<<<MDIM / MT, 256, smem_bytes>>>(sentence, proj);
    k_simw<<<BDIM, 128>>>(size_arr);
    k_combine<<<(LDIM * BDIM * (DDIM / 4)) / 256, 256>>>(sentence, out);
}

// round 5
// speedup vs baseline: 1.5340x; 1.0349x over previous
#include <cuda_runtime.h>
#include <cuda_fp16.h>
#include <cstdint>

// Problem dims
#define LDIM 128
#define BDIM 2048
#define DDIM 300
#define HDIM 60
#define HPAD 64
#define MDIM (LDIM * BDIM)  // 262144

// GEMM tiling
#define KC   32            // K per chunk
#define NCH  10            // ceil(300/32), K padded to 320
#define MT   256           // M rows per block
#define SAS  36            // sA row stride (floats): conflict-free fragment reads

// Scratch (static device globals — no allocation)
__device__ __half  g_q[(size_t)MDIM * HPAD];    // projected (fp16), padded to 64 cols
__device__ float2  g_w[MDIM];                   // (w0, w2); w1 = 1 - w0 - w2
__device__ float2  g_bpack[NCH * 1024];         // pre-packed B fragments per chunk

__device__ __forceinline__ uint32_t smem_u32(const void* p) {
    uint32_t a;
    asm("{ .reg .u64 t; cvta.to.shared.u64 t, %1; cvt.u32.u64 %0, t; }" : "=r"(a) : "l"(p));
    return a;
}
__device__ __forceinline__ uint32_t f2tf32(float x) {
    uint32_t u;
    asm("cvt.rna.tf32.f32 %0, %1;" : "=r"(u) : "f"(x));
    return u;
}
__device__ __forceinline__ void mma_tf32(float* c, uint32_t a0, uint32_t a1,
                                         uint32_t a2, uint32_t a3,
                                         uint32_t b0, uint32_t b1) {
    asm volatile(
        "mma.sync.aligned.m16n8k8.row.col.f32.tf32.tf32.f32 "
        "{%0,%1,%2,%3}, {%4,%5,%6,%7}, {%8,%9}, {%0,%1,%2,%3};"
        : "+f"(c[0]), "+f"(c[1]), "+f"(c[2]), "+f"(c[3])
        : "r"(a0), "r"(a1), "r"(a2), "r"(a3), "r"(b0), "r"(b1));
}
__device__ __forceinline__ void cp16(uint32_t dst, const void* src, int sz) {
    asm volatile("cp.async.cg.shared.global [%0], [%1], 16, %2;"
                 :: "r"(dst), "l"(src), "r"(sz));
}
#define CP_COMMIT() asm volatile("cp.async.commit_group;" ::: "memory")
#define CP_WAIT0()  asm volatile("cp.async.wait_group 0;" ::: "memory")

// ---------------------------------------------------------------------------
// Kernel 0 (one-shot, tiny): pack B fragments for all chunks.
// ---------------------------------------------------------------------------
__global__ void k_packB(const float* __restrict__ P) {
    const int e = blockIdx.x * 256 + threadIdx.x;   // < 10240
    if (e >= NCH * 1024) return;
    const int c  = e >> 10;
    const int r  = e & 1023;
    const int ks = r >> 8;
    const int n  = (r >> 5) & 7;
    const int ln = r & 31;
    const int tg = ln & 3, g = ln >> 2;
    const int k  = c * KC + 8 * ks + tg;
    const int h  = 8 * n + g;
    float b0 = (k < DDIM && h < HDIM)     ? P[(size_t)k * HDIM + h]       : 0.f;
    float b1 = (k + 4 < DDIM && h < HDIM) ? P[(size_t)(k + 4) * HDIM + h] : 0.f;
    float2 v;
    v.x = __uint_as_float(f2tf32(b0));
    v.y = __uint_as_float(f2tf32(b1));
    g_bpack[e] = v;
}

// ---------------------------------------------------------------------------
// Kernel 1: q = sentence @ proj via m16n8k8 tf32, double-buffered cp.async A.
// 256 threads / 8 warps; M=256 per block (2 m16 tiles/warp), N=64.
// ---------------------------------------------------------------------------
__global__ __launch_bounds__(256, 2) void k_gemm_mma(const float* __restrict__ A,
                                                     const float* __restrict__ P) {
    extern __shared__ float sm[];
    float*  sA  = sm;                                            // [2][MT][SAS]
    float2* sBp = reinterpret_cast<float2*>(sm + 2 * MT * SAS);  // [2][1024]
    const uint32_t* sAu = reinterpret_cast<const uint32_t*>(sm);

    const int tid  = threadIdx.x;
    const int w    = tid >> 5;
    const int lane = tid & 31;
    const int g    = lane >> 2;
    const int tig  = lane & 3;
    const int bm   = blockIdx.x * MT;

    const float*   arow = A + (size_t)(bm + tid) * DDIM;
    const uint32_t sA_u = smem_u32(sA);

    float acc0[8][4], acc1[8][4];
#pragma unroll
    for (int n = 0; n < 8; ++n)
#pragma unroll
        for (int i = 0; i < 4; ++i) { acc0[n][i] = 0.f; acc1[n][i] = 0.f; }

    auto stageA = [&](int c, int buf) {
#pragma unroll
        for (int i = 0; i < 8; ++i) {
            const int k  = c * KC + 4 * i;
            const int sz = (k + 4 <= DDIM) ? 16 : 0;
            const float* src = sz ? (arow + k) : A;
            const uint32_t dst = sA_u + (((buf * MT + tid) * SAS + 4 * i) << 2);
            cp16(dst, src, sz);
        }
    };
    auto stageB = [&](int c, int buf) {
#pragma unroll
        for (int e = 0; e < 4; ++e) {
            const int idx = tid + 256 * e;
            sBp[buf * 1024 + idx] = g_bpack[c * 1024 + idx];
        }
    };

    stageA(0, 0);
    CP_COMMIT();
    stageB(0, 0);

    const int rbase = 32 * w + g;

    for (int c = 0; c < NCH; ++c) {
        const int buf = c & 1;
        CP_WAIT0();
        __syncthreads();

        if (c + 1 < NCH) {
            stageA(c + 1, buf ^ 1);
            CP_COMMIT();
            stageB(c + 1, buf ^ 1);
        }

#pragma unroll
        for (int ks = 0; ks < 4; ++ks) {
            const int kk = 8 * ks;
            const int r0 = (buf * MT + rbase) * SAS + kk + tig;
            const uint32_t a00 = sAu[r0];
            const uint32_t a01 = sAu[r0 + 8 * SAS];
            const uint32_t a02 = sAu[r0 + 4];
            const uint32_t a03 = sAu[r0 + 8 * SAS + 4];
            const uint32_t a10 = sAu[r0 + 16 * SAS];
            const uint32_t a11 = sAu[r0 + 24 * SAS];
            const uint32_t a12 = sAu[r0 + 16 * SAS + 4];
            const uint32_t a13 = sAu[r0 + 24 * SAS + 4];
#pragma unroll
            for (int n = 0; n < 8; ++n) {
                const float2 b = sBp[buf * 1024 + (ks * 8 + n) * 32 + lane];
                const uint32_t b0 = __float_as_uint(b.x);
                const uint32_t b1 = __float_as_uint(b.y);
                mma_tf32(acc0[n], a00, a01, a02, a03, b0, b1);
                mma_tf32(acc1[n], a10, a11, a12, a13, b0, b1);
            }
        }
    }

    // ---- epilogue: fp16 q; thread writes half2 (cols 2tig,2tig+1) per n, 4 rows
    __half* d00 = g_q + ((size_t)bm + rbase) * HPAD;
    __half* d01 = g_q + ((size_t)bm + rbase + 8) * HPAD;
    __half* d10 = g_q + ((size_t)bm + rbase + 16) * HPAD;
    __half* d11 = g_q + ((size_t)bm + rbase + 24) * HPAD;
#pragma unroll
    for (int n = 0; n < 8; ++n) {
        const int col = 8 * n + 2 * tig;
        *reinterpret_cast<__half2*>(d00 + col) = __floats2half2_rn(acc0[n][0], acc0[n][1]);
        *reinterpret_cast<__half2*>(d01 + col) = __floats2half2_rn(acc0[n][2], acc0[n][3]);
        *reinterpret_cast<__half2*>(d10 + col) = __floats2half2_rn(acc1[n][0], acc1[n][1]);
        *reinterpret_cast<__half2*>(d11 + col) = __floats2half2_rn(acc1[n][2], acc1[n][3]);
    }
}

// ---------------------------------------------------------------------------
// Kernel 2: per-b column — row norms, neighbor dots, masked 3-way softmax.
// q rows are fp16: lane reads one half2 (cols 2lane, 2lane+1).
// ---------------------------------------------------------------------------
__global__ __launch_bounds__(128) void k_simw(const int* __restrict__ size) {
    const int b    = blockIdx.x;
    const int tid  = threadIdx.x;
    const int w    = tid >> 5;
    const int lane = tid & 31;

    __shared__ float nrm[LDIM];
    __shared__ float crs[LDIM];

    const int r0 = w * 32;
    float2 p = make_float2(0.f, 0.f);
    if (w > 0) {
        const __half2* row = reinterpret_cast<const __half2*>(
            g_q + ((size_t)(r0 - 1) * BDIM + b) * HPAD);
        p = __half22float2(row[lane]);
    }
    for (int r = r0; r < r0 + 32; ++r) {
        const __half2* row = reinterpret_cast<const __half2*>(
            g_q + ((size_t)r * BDIM + b) * HPAD);
        float2 v = __half22float2(row[lane]);
        float nn = v.x * v.x + v.y * v.y;
        float cc = v.x * p.x + v.y * p.y;
#pragma unroll
        for (int off = 16; off; off >>= 1) {
            nn += __shfl_xor_sync(0xffffffffu, nn, off);
            cc += __shfl_xor_sync(0xffffffffu, cc, off);
        }
        if (lane == 0) {
            nrm[r] = fmaxf(nn, 1e-5f);
            if (r > 0) crs[r - 1] = cc;
        }
        p = v;
    }
    __syncthreads();

    const int l  = tid;
    const int sz = size[b];
    float a0 = -1e30f, a2 = -1e30f;
    if (l >= 1 && l < sz)
        a0 = crs[l - 1] / (nrm[l - 1] * nrm[l]);
    int lim2 = sz - 1; if (lim2 < 0) lim2 = 0;
    if (l < lim2)
        a2 = crs[l] / (nrm[l] * nrm[l + 1]);

    float mx = fmaxf(1.0f, fmaxf(a0, a2));
    float e0 = expf(a0 - mx);
    float e1 = expf(1.0f - mx);
    float e2 = expf(a2 - mx);
    float inv = 1.0f / (e0 + e1 + e2);
    g_w[l * BDIM + b] = make_float2(e0 * inv, e2 * inv);
}

// ---------------------------------------------------------------------------
// Kernel 3: out[l,b,:] = w1*s[l] + w0*s[l-1] + w2*s[l+1].
// Thread owns one (b, j) column, walks l with register rotation: every
// sentence element is loaded exactly once. Streaming cache hints.
// Boundary: w0==0 at l=0 and w2==0 at l=127 by masking, so zero-filled
// prev/nxt registers are exact.
// ---------------------------------------------------------------------------
#define LSTRIDE ((size_t)BDIM * 75)   // float4 stride between l-planes

__global__ __launch_bounds__(256) void k_combine(const float* __restrict__ S,
                                                 float* __restrict__ out) {
    const int idx = blockIdx.x * 256 + threadIdx.x;  // < 153600
    const int b   = idx / 75;
    const int j   = idx - b * 75;

    const float4* sp = reinterpret_cast<const float4*>(S) + (size_t)b * 75 + j;
    float4*       op = reinterpret_cast<float4*>(out) + (size_t)b * 75 + j;
    const float2* wp = g_w + b;

    float4 prev = make_float4(0.f, 0.f, 0.f, 0.f);
    float4 cur  = __ldcs(sp);
    float4 nxt;

#pragma unroll 4
    for (int l = 0; l < LDIM; ++l) {
        if (l < LDIM - 1) nxt = __ldcs(sp + (size_t)(l + 1) * LSTRIDE);
        else              nxt = make_float4(0.f, 0.f, 0.f, 0.f);

        const float2 ww = __ldg(wp + (size_t)l * BDIM);
        const float w0 = ww.x, w2 = ww.y, w1 = 1.0f - w0 - w2;

        float4 r;
        r.x = w1 * cur.x; r.y = w1 * cur.y; r.z = w1 * cur.z; r.w = w1 * cur.w;
        r.x = fmaf(w0, prev.x, r.x); r.y = fmaf(w0, prev.y, r.y);
        r.z = fmaf(w0, prev.z, r.z); r.w = fmaf(w0, prev.w, r.w);
        r.x = fmaf(w2, nxt.x, r.x);  r.y = fmaf(w2, nxt.y, r.y);
        r.z = fmaf(w2, nxt.z, r.z);  r.w = fmaf(w2, nxt.w, r.w);

        __stcs(op + (size_t)l * LSTRIDE, r);
        prev = cur;
        cur  = nxt;
    }
}

// ---------------------------------------------------------------------------
extern "C" void kernel_launch(void* const* d_in, const int* in_sizes, int n_in,
                              void* d_out, int out_size) {
    const float* sentence = nullptr;
    const int*   size_arr = nullptr;
    const float* proj     = nullptr;
    for (int i = 0; i < n_in; ++i) {
        if (in_sizes[i] == LDIM * BDIM * DDIM)      sentence = (const float*)d_in[i];
        else if (in_sizes[i] == DDIM * HDIM)        proj     = (const float*)d_in[i];
        else if (in_sizes[i] == BDIM)               size_arr = (const int*)d_in[i];
    }
    float* out = (float*)d_out;

    const int smem_bytes = (2 * MT * SAS) * 4 + 2 * 1024 * 8;   // 90112
    cudaFuncSetAttribute(k_gemm_mma, cudaFuncAttributeMaxDynamicSharedMemorySize,
                         smem_bytes);

    k_packB<<<(NCH * 1024 + 255) / 256, 256>>>(proj);
    k_gemm_mma<<<MDIM / MT, 256, smem_bytes>>>(sentence, proj);
    k_simw<<<BDIM, 128>>>(size_arr);
    k_combine<<<(BDIM * 75) / 256, 256>>>(sentence, out);
}